// round 3
// baseline (speedup 1.0000x reference)
#include <cuda_runtime.h>
#include <cstdint>

#define N_NODES 50000
#define N_EDGES 500000
#define SD 128
#define VD 3
#define HID 64
#define DEPTH 4
#define CUTOFF 5.0f

// W3 row stride padded to 136 floats for float4 alignment
#define W3_PAD 136

// ---------------- scratch state (no allocations allowed) ----------------
__device__ float g_s[N_NODES * SD];        // current node scalars
__device__ float g_v[N_NODES * VD * 3];    // current node vectors
__device__ float g_sagg[N_NODES * SD];     // per-layer scalar aggregate
__device__ float g_vagg[N_NODES * VD * 3]; // per-layer vector aggregate
__device__ float g_cnt[N_NODES];
__device__ float g_inv[N_NODES];
__device__ float g_C[N_EDGES];

__device__ __forceinline__ float silu(float x) {
    return x / (1.0f + __expf(-x));
}

__device__ __forceinline__ void red_add4(float* p, float a, float b, float c, float d) {
    asm volatile("red.global.add.v4.f32 [%0], {%1,%2,%3,%4};"
                 :: "l"(p), "f"(a), "f"(b), "f"(c), "f"(d) : "memory");
}
__device__ __forceinline__ void red_add1(float* p, float a) {
    asm volatile("red.global.add.f32 [%0], %1;" :: "l"(p), "f"(a) : "memory");
}

// ---------------- prep kernels ----------------
__global__ void init_state(const float* __restrict__ s, const float* __restrict__ v) {
    int i = blockIdx.x * blockDim.x + threadIdx.x;
    int stride = gridDim.x * blockDim.x;
    for (int k = i; k < N_NODES * SD; k += stride) g_s[k] = s[k];
    for (int k = i; k < N_NODES * VD * 3; k += stride) g_v[k] = v[k];
    for (int k = i; k < N_NODES; k += stride) g_cnt[k] = 0.0f;
}

__global__ void prep_edges(const int* __restrict__ ei, const float* __restrict__ d) {
    int e = blockIdx.x * blockDim.x + threadIdx.x;
    if (e >= N_EDGES) return;
    int dst = ei[e];
    red_add1(&g_cnt[dst], 1.0f);
    float dd = d[e];
    float c = 0.5f * (cospif(dd * (1.0f / CUTOFF)) + 1.0f);
    g_C[e] = (dd < CUTOFF) ? c : 0.0f;
}

__global__ void compute_inv() {
    int n = blockIdx.x * blockDim.x + threadIdx.x;
    if (n < N_NODES) g_inv[n] = 1.0f / fmaxf(g_cnt[n], 1.0f);
}

__global__ void zero_agg() {
    int i = blockIdx.x * blockDim.x + threadIdx.x;
    int stride = gridDim.x * blockDim.x;
    for (int k = i; k < N_NODES * SD; k += stride) g_sagg[k] = 0.0f;
    for (int k = i; k < N_NODES * VD * 3; k += stride) g_vagg[k] = 0.0f;
}

// ---------------- fused edge MLP + scatter ----------------
// one thread = one edge; weights for this layer staged in smem (broadcast reads)
__global__ __launch_bounds__(256) void edge_kernel(
    const int* __restrict__ ei, const float* __restrict__ d, const float* __restrict__ r,
    const float* __restrict__ W1, const float* __restrict__ b1,
    const float* __restrict__ W2, const float* __restrict__ b2,
    const float* __restrict__ W3, const float* __restrict__ b3, int layer)
{
    extern __shared__ float sm[];
    float* W1s = sm;                       // 257*64
    float* W2s = W1s + 257 * HID;          // 64*64
    float* W3s = W2s + HID * HID;          // 64*136 (padded)
    float* b1s = W3s + HID * W3_PAD;       // 64
    float* b2s = b1s + HID;                // 64
    float* b3s = b2s + HID;                // 136

    const float* W1g = W1 + (size_t)layer * 257 * HID;
    const float* W2g = W2 + (size_t)layer * HID * HID;
    const float* W3g = W3 + (size_t)layer * HID * 134;

    for (int i = threadIdx.x; i < 257 * HID; i += blockDim.x) W1s[i] = W1g[i];
    for (int i = threadIdx.x; i < HID * HID; i += blockDim.x) W2s[i] = W2g[i];
    for (int i = threadIdx.x; i < HID * 134; i += blockDim.x) {
        int row = i / 134, col = i - row * 134;
        W3s[row * W3_PAD + col] = W3g[i];
    }
    for (int i = threadIdx.x; i < HID; i += blockDim.x) {
        b1s[i] = b1[layer * HID + i];
        b2s[i] = b2[layer * HID + i];
    }
    for (int i = threadIdx.x; i < 134; i += blockDim.x) b3s[i] = b3[layer * 134 + i];
    __syncthreads();

    int e = blockIdx.x * blockDim.x + threadIdx.x;
    if (e >= N_EDGES) return;

    int dst = ei[e];
    int src = ei[N_EDGES + e];
    float C = g_C[e];

    // ---- h1 = silu([s_dst, s_src, d] @ W1 + b1) ----
    float h1[HID];
#pragma unroll
    for (int j = 0; j < HID; j++) h1[j] = b1s[j];

    const float4* xd = reinterpret_cast<const float4*>(g_s + (size_t)dst * SD);
    const float4* xs = reinterpret_cast<const float4*>(g_s + (size_t)src * SD);

#pragma unroll 4
    for (int kk = 0; kk < SD / 4; kk++) {
        float4 xv = xd[kk];
        float xr[4] = {xv.x, xv.y, xv.z, xv.w};
#pragma unroll
        for (int t = 0; t < 4; t++) {
            const float4* wrow = reinterpret_cast<const float4*>(W1s + (kk * 4 + t) * HID);
            float xk = xr[t];
#pragma unroll
            for (int j4 = 0; j4 < HID / 4; j4++) {
                float4 w = wrow[j4];
                h1[j4*4+0] += xk * w.x; h1[j4*4+1] += xk * w.y;
                h1[j4*4+2] += xk * w.z; h1[j4*4+3] += xk * w.w;
            }
        }
    }
#pragma unroll 4
    for (int kk = 0; kk < SD / 4; kk++) {
        float4 xv = xs[kk];
        float xr[4] = {xv.x, xv.y, xv.z, xv.w};
#pragma unroll
        for (int t = 0; t < 4; t++) {
            const float4* wrow = reinterpret_cast<const float4*>(W1s + (SD + kk * 4 + t) * HID);
            float xk = xr[t];
#pragma unroll
            for (int j4 = 0; j4 < HID / 4; j4++) {
                float4 w = wrow[j4];
                h1[j4*4+0] += xk * w.x; h1[j4*4+1] += xk * w.y;
                h1[j4*4+2] += xk * w.z; h1[j4*4+3] += xk * w.w;
            }
        }
    }
    {
        float xk = d[e];
        const float4* wrow = reinterpret_cast<const float4*>(W1s + 256 * HID);
#pragma unroll
        for (int j4 = 0; j4 < HID / 4; j4++) {
            float4 w = wrow[j4];
            h1[j4*4+0] += xk * w.x; h1[j4*4+1] += xk * w.y;
            h1[j4*4+2] += xk * w.z; h1[j4*4+3] += xk * w.w;
        }
    }
#pragma unroll
    for (int j = 0; j < HID; j++) h1[j] = silu(h1[j]);

    // ---- h2 = silu(h1 @ W2 + b2) ----
    float h2[HID];
#pragma unroll
    for (int j = 0; j < HID; j++) h2[j] = b2s[j];
#pragma unroll 4
    for (int k = 0; k < HID; k++) {
        float hk = h1[k];
        const float4* wrow = reinterpret_cast<const float4*>(W2s + k * HID);
#pragma unroll
        for (int j4 = 0; j4 < HID / 4; j4++) {
            float4 w = wrow[j4];
            h2[j4*4+0] += hk * w.x; h2[j4*4+1] += hk * w.y;
            h2[j4*4+2] += hk * w.z; h2[j4*4+3] += hk * w.w;
        }
    }
#pragma unroll
    for (int j = 0; j < HID; j++) h2[j] = silu(h2[j]);

    // ---- m = h2 @ W3 + b3 ; scatter ms*C and vm ----
    float* sbase = g_sagg + (size_t)dst * SD;
#pragma unroll 1
    for (int c = 0; c < 4; c++) {
        float acc[32];
#pragma unroll
        for (int j = 0; j < 32; j++) acc[j] = b3s[c * 32 + j];
#pragma unroll 4
        for (int k = 0; k < HID; k++) {
            float hk = h2[k];
            const float4* wrow = reinterpret_cast<const float4*>(W3s + k * W3_PAD + c * 32);
#pragma unroll
            for (int j4 = 0; j4 < 8; j4++) {
                float4 w = wrow[j4];
                acc[j4*4+0] += hk * w.x; acc[j4*4+1] += hk * w.y;
                acc[j4*4+2] += hk * w.z; acc[j4*4+3] += hk * w.w;
            }
        }
#pragma unroll
        for (int j4 = 0; j4 < 8; j4++)
            red_add4(sbase + c * 32 + j4 * 4,
                     acc[j4*4+0] * C, acc[j4*4+1] * C, acc[j4*4+2] * C, acc[j4*4+3] * C);
    }

    // gv, gr (columns 128..133)
    float g6[6];
#pragma unroll
    for (int j = 0; j < 6; j++) g6[j] = b3s[SD + j];
#pragma unroll 4
    for (int k = 0; k < HID; k++) {
        float hk = h2[k];
#pragma unroll
        for (int j = 0; j < 6; j++) g6[j] += hk * W3s[k * W3_PAD + SD + j];
    }
    float rr0 = r[e * 3 + 0], rr1 = r[e * 3 + 1], rr2 = r[e * 3 + 2];
    const float* vs = g_v + (size_t)src * 9;
    float* vdp = g_vagg + (size_t)dst * 9;
#pragma unroll
    for (int a = 0; a < 3; a++) {
        float gva = g6[a] * C, gra = g6[3 + a] * C;
        red_add1(vdp + a * 3 + 0, vs[a * 3 + 0] * gva + rr0 * gra);
        red_add1(vdp + a * 3 + 1, vs[a * 3 + 1] * gva + rr1 * gra);
        red_add1(vdp + a * 3 + 2, vs[a * 3 + 2] * gva + rr2 * gra);
    }
}

// ---------------- fused node MLP + residual updates ----------------
__global__ __launch_bounds__(256) void node_kernel(
    const float* __restrict__ Wn1, const float* __restrict__ bn1,
    const float* __restrict__ Wn2, const float* __restrict__ bn2, int layer)
{
    extern __shared__ float sm[];
    float* W1s = sm;                     // 256*64
    float* W2s = W1s + 2 * SD * HID;     // 64*128
    float* b1s = W2s + HID * SD;         // 64
    float* b2s = b1s + HID;              // 128

    const float* W1g = Wn1 + (size_t)layer * 2 * SD * HID;
    const float* W2g = Wn2 + (size_t)layer * HID * SD;
    for (int i = threadIdx.x; i < 2 * SD * HID; i += blockDim.x) W1s[i] = W1g[i];
    for (int i = threadIdx.x; i < HID * SD; i += blockDim.x) W2s[i] = W2g[i];
    for (int i = threadIdx.x; i < HID; i += blockDim.x) b1s[i] = bn1[layer * HID + i];
    for (int i = threadIdx.x; i < SD; i += blockDim.x) b2s[i] = bn2[layer * SD + i];
    __syncthreads();

    int n = blockIdx.x * blockDim.x + threadIdx.x;
    if (n >= N_NODES) return;

    float u[HID];
#pragma unroll
    for (int j = 0; j < HID; j++) u[j] = b1s[j];

    const float4* xs = reinterpret_cast<const float4*>(g_s + (size_t)n * SD);
    const float4* xa = reinterpret_cast<const float4*>(g_sagg + (size_t)n * SD);

#pragma unroll 4
    for (int kk = 0; kk < SD / 4; kk++) {
        float4 xv = xs[kk];
        float xr[4] = {xv.x, xv.y, xv.z, xv.w};
#pragma unroll
        for (int t = 0; t < 4; t++) {
            const float4* wrow = reinterpret_cast<const float4*>(W1s + (kk * 4 + t) * HID);
            float xk = xr[t];
#pragma unroll
            for (int j4 = 0; j4 < HID / 4; j4++) {
                float4 w = wrow[j4];
                u[j4*4+0] += xk * w.x; u[j4*4+1] += xk * w.y;
                u[j4*4+2] += xk * w.z; u[j4*4+3] += xk * w.w;
            }
        }
    }
#pragma unroll 4
    for (int kk = 0; kk < SD / 4; kk++) {
        float4 xv = xa[kk];
        float xr[4] = {xv.x, xv.y, xv.z, xv.w};
#pragma unroll
        for (int t = 0; t < 4; t++) {
            const float4* wrow = reinterpret_cast<const float4*>(W1s + (SD + kk * 4 + t) * HID);
            float xk = xr[t];
#pragma unroll
            for (int j4 = 0; j4 < HID / 4; j4++) {
                float4 w = wrow[j4];
                u[j4*4+0] += xk * w.x; u[j4*4+1] += xk * w.y;
                u[j4*4+2] += xk * w.z; u[j4*4+3] += xk * w.w;
            }
        }
    }
#pragma unroll
    for (int j = 0; j < HID; j++) u[j] = silu(u[j]);

    float* sp = g_s + (size_t)n * SD;
#pragma unroll 1
    for (int c = 0; c < 4; c++) {
        float acc[32];
#pragma unroll
        for (int j = 0; j < 32; j++) acc[j] = b2s[c * 32 + j];
#pragma unroll 4
        for (int k = 0; k < HID; k++) {
            float hk = u[k];
            const float4* wrow = reinterpret_cast<const float4*>(W2s + k * SD + c * 32);
#pragma unroll
            for (int j4 = 0; j4 < 8; j4++) {
                float4 w = wrow[j4];
                acc[j4*4+0] += hk * w.x; acc[j4*4+1] += hk * w.y;
                acc[j4*4+2] += hk * w.z; acc[j4*4+3] += hk * w.w;
            }
        }
#pragma unroll
        for (int j = 0; j < 32; j++) sp[c * 32 + j] += acc[j];
    }

    float inv = g_inv[n];
    float* vp = g_v + (size_t)n * 9;
    const float* va = g_vagg + (size_t)n * 9;
#pragma unroll
    for (int i = 0; i < 9; i++) vp[i] += va[i] * inv;
}

__global__ void write_out(float* __restrict__ out) {
    int i = blockIdx.x * blockDim.x + threadIdx.x;
    int stride = gridDim.x * blockDim.x;
    for (int k = i; k < N_NODES * SD; k += stride) out[k] = g_s[k];
    for (int k = i; k < N_NODES * VD * 3; k += stride) out[N_NODES * SD + k] = g_v[k];
}

// ---------------- launch ----------------
extern "C" void kernel_launch(void* const* d_in, const int* in_sizes, int n_in,
                              void* d_out, int out_size) {
    const float* s   = (const float*)d_in[0];
    const float* v   = (const float*)d_in[1];
    const int*   ei  = (const int*)d_in[2];
    const float* d   = (const float*)d_in[3];
    const float* r   = (const float*)d_in[4];
    const float* W1  = (const float*)d_in[5];
    const float* b1  = (const float*)d_in[6];
    const float* W2  = (const float*)d_in[7];
    const float* b2  = (const float*)d_in[8];
    const float* W3  = (const float*)d_in[9];
    const float* b3  = (const float*)d_in[10];
    const float* Wn1 = (const float*)d_in[11];
    const float* bn1 = (const float*)d_in[12];
    const float* Wn2 = (const float*)d_in[13];
    const float* bn2 = (const float*)d_in[14];
    float* out = (float*)d_out;

    const int edge_smem = (257 * HID + HID * HID + HID * W3_PAD + HID + HID + W3_PAD) * 4;
    const int node_smem = (2 * SD * HID + HID * SD + HID + SD) * 4;
    cudaFuncSetAttribute(edge_kernel, cudaFuncAttributeMaxDynamicSharedMemorySize, edge_smem);
    cudaFuncSetAttribute(node_kernel, cudaFuncAttributeMaxDynamicSharedMemorySize, node_smem);

    init_state<<<1024, 256>>>(s, v);
    prep_edges<<<(N_EDGES + 255) / 256, 256>>>(ei, d);
    compute_inv<<<(N_NODES + 255) / 256, 256>>>();

    for (int l = 0; l < DEPTH; l++) {
        zero_agg<<<1024, 256>>>();
        edge_kernel<<<(N_EDGES + 255) / 256, 256, edge_smem>>>(ei, d, r, W1, b1, W2, b2, W3, b3, l);
        node_kernel<<<(N_NODES + 255) / 256, 256, node_smem>>>(Wn1, bn1, Wn2, bn2, l);
    }
    write_out<<<1024, 256>>>(out);
}

// round 4
// speedup vs baseline: 1.2300x; 1.2300x over previous
#include <cuda_runtime.h>
#include <cstdint>

#define N_NODES 50000
#define N_EDGES 500000
#define SD 128
#define VD 3
#define HID 64
#define DEPTH 4
#define CUTOFF 5.0f

// W3 row stride padded to 136 floats for 16B alignment
#define W3_PAD 136

// ---------------- scratch state (no allocations allowed) ----------------
__device__ float g_s[N_NODES * SD];        // current node scalars
__device__ float g_v[N_NODES * VD * 3];    // current node vectors
__device__ float g_sagg[N_NODES * SD];     // per-layer scalar aggregate
__device__ float g_vagg[N_NODES * VD * 3]; // per-layer vector aggregate
__device__ float g_cnt[N_NODES];
__device__ float g_inv[N_NODES];
__device__ float g_C[N_EDGES];

__device__ __forceinline__ float silu(float x) {
    return x / (1.0f + __expf(-x));
}

// ---------------- packed f32x2 helpers (FFMA2 path, ptxas won't emit it) ----
__device__ __forceinline__ unsigned long long pack2(float x) {
    unsigned long long p;
    unsigned int u = __float_as_uint(x);
    asm("mov.b64 %0, {%1, %1};" : "=l"(p) : "r"(u));
    return p;
}
__device__ __forceinline__ void unpack2(unsigned long long p, float& lo, float& hi) {
    unsigned int a, b;
    asm("mov.b64 {%0, %1}, %2;" : "=r"(a), "=r"(b) : "l"(p));
    lo = __uint_as_float(a);
    hi = __uint_as_float(b);
}
__device__ __forceinline__ void fma2(unsigned long long& acc,
                                     unsigned long long a, unsigned long long b) {
    asm("fma.rn.f32x2 %0, %1, %2, %0;" : "+l"(acc) : "l"(a), "l"(b));
}
__device__ __forceinline__ unsigned long long mul2(unsigned long long a,
                                                   unsigned long long b) {
    unsigned long long d;
    asm("mul.rn.f32x2 %0, %1, %2;" : "=l"(d) : "l"(a), "l"(b));
    return d;
}

__device__ __forceinline__ void red_add4(float* p, float a, float b, float c, float d) {
    asm volatile("red.global.add.v4.f32 [%0], {%1,%2,%3,%4};"
                 :: "l"(p), "f"(a), "f"(b), "f"(c), "f"(d) : "memory");
}
__device__ __forceinline__ void red_add1(float* p, float a) {
    asm volatile("red.global.add.f32 [%0], %1;" :: "l"(p), "f"(a) : "memory");
}

// ---------------- prep kernels ----------------
__global__ void init_state(const float* __restrict__ s, const float* __restrict__ v) {
    int i = blockIdx.x * blockDim.x + threadIdx.x;
    int stride = gridDim.x * blockDim.x;
    for (int k = i; k < N_NODES * SD; k += stride) g_s[k] = s[k];
    for (int k = i; k < N_NODES * VD * 3; k += stride) g_v[k] = v[k];
    for (int k = i; k < N_NODES; k += stride) g_cnt[k] = 0.0f;
}

__global__ void prep_edges(const int* __restrict__ ei, const float* __restrict__ d) {
    int e = blockIdx.x * blockDim.x + threadIdx.x;
    if (e >= N_EDGES) return;
    int dst = ei[e];
    red_add1(&g_cnt[dst], 1.0f);
    float dd = d[e];
    float c = 0.5f * (cospif(dd * (1.0f / CUTOFF)) + 1.0f);
    g_C[e] = (dd < CUTOFF) ? c : 0.0f;
}

__global__ void compute_inv() {
    int n = blockIdx.x * blockDim.x + threadIdx.x;
    if (n < N_NODES) g_inv[n] = 1.0f / fmaxf(g_cnt[n], 1.0f);
}

__global__ void zero_agg() {
    int i = blockIdx.x * blockDim.x + threadIdx.x;
    int stride = gridDim.x * blockDim.x;
    for (int k = i; k < N_NODES * SD; k += stride) g_sagg[k] = 0.0f;
    for (int k = i; k < N_NODES * VD * 3; k += stride) g_vagg[k] = 0.0f;
}

// ---------------- fused edge MLP + scatter (f32x2 packed math) ----------------
__global__ __launch_bounds__(256) void edge_kernel(
    const int* __restrict__ ei, const float* __restrict__ d, const float* __restrict__ r,
    const float* __restrict__ W1, const float* __restrict__ b1,
    const float* __restrict__ W2, const float* __restrict__ b2,
    const float* __restrict__ W3, const float* __restrict__ b3, int layer)
{
    extern __shared__ float sm[];
    float* W1s = sm;                       // 257*64
    float* W2s = W1s + 257 * HID;          // 64*64
    float* W3s = W2s + HID * HID;          // 64*136 (padded)
    float* b1s = W3s + HID * W3_PAD;       // 64
    float* b2s = b1s + HID;                // 64
    float* b3s = b2s + HID;                // 136

    const float* W1g = W1 + (size_t)layer * 257 * HID;
    const float* W2g = W2 + (size_t)layer * HID * HID;
    const float* W3g = W3 + (size_t)layer * HID * 134;

    for (int i = threadIdx.x; i < 257 * HID; i += blockDim.x) W1s[i] = W1g[i];
    for (int i = threadIdx.x; i < HID * HID; i += blockDim.x) W2s[i] = W2g[i];
    for (int i = threadIdx.x; i < HID * 134; i += blockDim.x) {
        int row = i / 134, col = i - row * 134;
        W3s[row * W3_PAD + col] = W3g[i];
    }
    for (int i = threadIdx.x; i < HID; i += blockDim.x) {
        b1s[i] = b1[layer * HID + i];
        b2s[i] = b2[layer * HID + i];
    }
    for (int i = threadIdx.x; i < 134; i += blockDim.x) b3s[i] = b3[layer * 134 + i];
    __syncthreads();

    int e = blockIdx.x * blockDim.x + threadIdx.x;
    if (e >= N_EDGES) return;

    int dst = ei[e];
    int src = ei[N_EDGES + e];
    float C = g_C[e];

    // ---- h1 = silu([s_dst, s_src, d] @ W1 + b1), packed over output pairs ----
    unsigned long long h1p[32];
    {
        const unsigned long long* b1p = (const unsigned long long*)b1s;
#pragma unroll
        for (int j = 0; j < 32; j++) h1p[j] = b1p[j];
    }

    const float4* xd = reinterpret_cast<const float4*>(g_s + (size_t)dst * SD);
    const float4* xs = reinterpret_cast<const float4*>(g_s + (size_t)src * SD);

#pragma unroll 4
    for (int kk = 0; kk < SD / 4; kk++) {
        float4 xv = xd[kk];
        float xr[4] = {xv.x, xv.y, xv.z, xv.w};
#pragma unroll
        for (int t = 0; t < 4; t++) {
            unsigned long long xk2 = pack2(xr[t]);
            const ulonglong2* wrow = reinterpret_cast<const ulonglong2*>(W1s + (kk * 4 + t) * HID);
#pragma unroll
            for (int q = 0; q < 16; q++) {
                ulonglong2 w = wrow[q];
                fma2(h1p[2 * q + 0], xk2, w.x);
                fma2(h1p[2 * q + 1], xk2, w.y);
            }
        }
    }
#pragma unroll 4
    for (int kk = 0; kk < SD / 4; kk++) {
        float4 xv = xs[kk];
        float xr[4] = {xv.x, xv.y, xv.z, xv.w};
#pragma unroll
        for (int t = 0; t < 4; t++) {
            unsigned long long xk2 = pack2(xr[t]);
            const ulonglong2* wrow = reinterpret_cast<const ulonglong2*>(W1s + (SD + kk * 4 + t) * HID);
#pragma unroll
            for (int q = 0; q < 16; q++) {
                ulonglong2 w = wrow[q];
                fma2(h1p[2 * q + 0], xk2, w.x);
                fma2(h1p[2 * q + 1], xk2, w.y);
            }
        }
    }
    {
        unsigned long long xk2 = pack2(d[e]);
        const ulonglong2* wrow = reinterpret_cast<const ulonglong2*>(W1s + 256 * HID);
#pragma unroll
        for (int q = 0; q < 16; q++) {
            ulonglong2 w = wrow[q];
            fma2(h1p[2 * q + 0], xk2, w.x);
            fma2(h1p[2 * q + 1], xk2, w.y);
        }
    }

    float h1[HID];
#pragma unroll
    for (int j = 0; j < 32; j++) {
        float lo, hi;
        unpack2(h1p[j], lo, hi);
        h1[2 * j + 0] = silu(lo);
        h1[2 * j + 1] = silu(hi);
    }

    // ---- h2 = silu(h1 @ W2 + b2) ----
    unsigned long long h2p[32];
    {
        const unsigned long long* b2p = (const unsigned long long*)b2s;
#pragma unroll
        for (int j = 0; j < 32; j++) h2p[j] = b2p[j];
    }
#pragma unroll 4
    for (int k = 0; k < HID; k++) {
        unsigned long long hk2 = pack2(h1[k]);
        const ulonglong2* wrow = reinterpret_cast<const ulonglong2*>(W2s + k * HID);
#pragma unroll
        for (int q = 0; q < 16; q++) {
            ulonglong2 w = wrow[q];
            fma2(h2p[2 * q + 0], hk2, w.x);
            fma2(h2p[2 * q + 1], hk2, w.y);
        }
    }
    float h2[HID];
#pragma unroll
    for (int j = 0; j < 32; j++) {
        float lo, hi;
        unpack2(h2p[j], lo, hi);
        h2[2 * j + 0] = silu(lo);
        h2[2 * j + 1] = silu(hi);
    }

    // ---- m = h2 @ W3 + b3 ; scatter ms*C and vector messages ----
    unsigned long long C2 = pack2(C);
    float* sbase = g_sagg + (size_t)dst * SD;

    unsigned long long g01, g23, g45;
    {
        const unsigned long long* gp = (const unsigned long long*)(b3s + SD);
        g01 = gp[0]; g23 = gp[1]; g45 = gp[2];
    }

#pragma unroll 1
    for (int c = 0; c < 4; c++) {
        unsigned long long acc[16];
        const unsigned long long* bp = (const unsigned long long*)(b3s + c * 32);
#pragma unroll
        for (int q = 0; q < 16; q++) acc[q] = bp[q];

        if (c == 0) {
#pragma unroll 4
            for (int k = 0; k < HID; k++) {
                unsigned long long hk2 = pack2(h2[k]);
                const ulonglong2* wrow = reinterpret_cast<const ulonglong2*>(W3s + k * W3_PAD);
#pragma unroll
                for (int q = 0; q < 8; q++) {
                    ulonglong2 w = wrow[q];
                    fma2(acc[2 * q + 0], hk2, w.x);
                    fma2(acc[2 * q + 1], hk2, w.y);
                }
                const unsigned long long* gw = (const unsigned long long*)(W3s + k * W3_PAD + SD);
                fma2(g01, hk2, gw[0]);
                fma2(g23, hk2, gw[1]);
                fma2(g45, hk2, gw[2]);
            }
        } else {
#pragma unroll 4
            for (int k = 0; k < HID; k++) {
                unsigned long long hk2 = pack2(h2[k]);
                const ulonglong2* wrow = reinterpret_cast<const ulonglong2*>(W3s + k * W3_PAD + c * 32);
#pragma unroll
                for (int q = 0; q < 8; q++) {
                    ulonglong2 w = wrow[q];
                    fma2(acc[2 * q + 0], hk2, w.x);
                    fma2(acc[2 * q + 1], hk2, w.y);
                }
            }
        }
#pragma unroll
        for (int q = 0; q < 8; q++) {
            unsigned long long p0 = mul2(acc[2 * q + 0], C2);
            unsigned long long p1 = mul2(acc[2 * q + 1], C2);
            float a0, a1, a2, a3;
            unpack2(p0, a0, a1);
            unpack2(p1, a2, a3);
            red_add4(sbase + c * 32 + q * 4, a0, a1, a2, a3);
        }
    }

    // vector part (gv, gr at columns 128..133)
    float g6[6];
    unpack2(g01, g6[0], g6[1]);
    unpack2(g23, g6[2], g6[3]);
    unpack2(g45, g6[4], g6[5]);

    float rr0 = r[e * 3 + 0], rr1 = r[e * 3 + 1], rr2 = r[e * 3 + 2];
    const float* vs = g_v + (size_t)src * 9;
    float* vdp = g_vagg + (size_t)dst * 9;
#pragma unroll
    for (int a = 0; a < 3; a++) {
        float gva = g6[a] * C, gra = g6[3 + a] * C;
        red_add1(vdp + a * 3 + 0, vs[a * 3 + 0] * gva + rr0 * gra);
        red_add1(vdp + a * 3 + 1, vs[a * 3 + 1] * gva + rr1 * gra);
        red_add1(vdp + a * 3 + 2, vs[a * 3 + 2] * gva + rr2 * gra);
    }
}

// ---------------- fused node MLP + residual updates (f32x2) ----------------
__global__ __launch_bounds__(256) void node_kernel(
    const float* __restrict__ Wn1, const float* __restrict__ bn1,
    const float* __restrict__ Wn2, const float* __restrict__ bn2, int layer)
{
    extern __shared__ float sm[];
    float* W1s = sm;                     // 256*64
    float* W2s = W1s + 2 * SD * HID;     // 64*128
    float* b1s = W2s + HID * SD;         // 64
    float* b2s = b1s + HID;              // 128

    const float* W1g = Wn1 + (size_t)layer * 2 * SD * HID;
    const float* W2g = Wn2 + (size_t)layer * HID * SD;
    for (int i = threadIdx.x; i < 2 * SD * HID; i += blockDim.x) W1s[i] = W1g[i];
    for (int i = threadIdx.x; i < HID * SD; i += blockDim.x) W2s[i] = W2g[i];
    for (int i = threadIdx.x; i < HID; i += blockDim.x) b1s[i] = bn1[layer * HID + i];
    for (int i = threadIdx.x; i < SD; i += blockDim.x) b2s[i] = bn2[layer * SD + i];
    __syncthreads();

    int n = blockIdx.x * blockDim.x + threadIdx.x;
    if (n >= N_NODES) return;

    unsigned long long up[32];
    {
        const unsigned long long* b1p = (const unsigned long long*)b1s;
#pragma unroll
        for (int j = 0; j < 32; j++) up[j] = b1p[j];
    }

    const float4* xs = reinterpret_cast<const float4*>(g_s + (size_t)n * SD);
    const float4* xa = reinterpret_cast<const float4*>(g_sagg + (size_t)n * SD);

#pragma unroll 4
    for (int kk = 0; kk < SD / 4; kk++) {
        float4 xv = xs[kk];
        float xr[4] = {xv.x, xv.y, xv.z, xv.w};
#pragma unroll
        for (int t = 0; t < 4; t++) {
            unsigned long long xk2 = pack2(xr[t]);
            const ulonglong2* wrow = reinterpret_cast<const ulonglong2*>(W1s + (kk * 4 + t) * HID);
#pragma unroll
            for (int q = 0; q < 16; q++) {
                ulonglong2 w = wrow[q];
                fma2(up[2 * q + 0], xk2, w.x);
                fma2(up[2 * q + 1], xk2, w.y);
            }
        }
    }
#pragma unroll 4
    for (int kk = 0; kk < SD / 4; kk++) {
        float4 xv = xa[kk];
        float xr[4] = {xv.x, xv.y, xv.z, xv.w};
#pragma unroll
        for (int t = 0; t < 4; t++) {
            unsigned long long xk2 = pack2(xr[t]);
            const ulonglong2* wrow = reinterpret_cast<const ulonglong2*>(W1s + (SD + kk * 4 + t) * HID);
#pragma unroll
            for (int q = 0; q < 16; q++) {
                ulonglong2 w = wrow[q];
                fma2(up[2 * q + 0], xk2, w.x);
                fma2(up[2 * q + 1], xk2, w.y);
            }
        }
    }

    float u[HID];
#pragma unroll
    for (int j = 0; j < 32; j++) {
        float lo, hi;
        unpack2(up[j], lo, hi);
        u[2 * j + 0] = silu(lo);
        u[2 * j + 1] = silu(hi);
    }

    float* sp = g_s + (size_t)n * SD;
#pragma unroll 1
    for (int c = 0; c < 4; c++) {
        unsigned long long acc[16];
        const unsigned long long* bp = (const unsigned long long*)(b2s + c * 32);
#pragma unroll
        for (int q = 0; q < 16; q++) acc[q] = bp[q];
#pragma unroll 4
        for (int k = 0; k < HID; k++) {
            unsigned long long hk2 = pack2(u[k]);
            const ulonglong2* wrow = reinterpret_cast<const ulonglong2*>(W2s + k * SD + c * 32);
#pragma unroll
            for (int q = 0; q < 8; q++) {
                ulonglong2 w = wrow[q];
                fma2(acc[2 * q + 0], hk2, w.x);
                fma2(acc[2 * q + 1], hk2, w.y);
            }
        }
#pragma unroll
        for (int q = 0; q < 16; q++) {
            float lo, hi;
            unpack2(acc[q], lo, hi);
            sp[c * 32 + 2 * q + 0] += lo;
            sp[c * 32 + 2 * q + 1] += hi;
        }
    }

    float inv = g_inv[n];
    float* vp = g_v + (size_t)n * 9;
    const float* va = g_vagg + (size_t)n * 9;
#pragma unroll
    for (int i = 0; i < 9; i++) vp[i] += va[i] * inv;
}

__global__ void write_out(float* __restrict__ out) {
    int i = blockIdx.x * blockDim.x + threadIdx.x;
    int stride = gridDim.x * blockDim.x;
    for (int k = i; k < N_NODES * SD; k += stride) out[k] = g_s[k];
    for (int k = i; k < N_NODES * VD * 3; k += stride) out[N_NODES * SD + k] = g_v[k];
}

// ---------------- launch ----------------
extern "C" void kernel_launch(void* const* d_in, const int* in_sizes, int n_in,
                              void* d_out, int out_size) {
    const float* s   = (const float*)d_in[0];
    const float* v   = (const float*)d_in[1];
    const int*   ei  = (const int*)d_in[2];
    const float* d   = (const float*)d_in[3];
    const float* r   = (const float*)d_in[4];
    const float* W1  = (const float*)d_in[5];
    const float* b1  = (const float*)d_in[6];
    const float* W2  = (const float*)d_in[7];
    const float* b2  = (const float*)d_in[8];
    const float* W3  = (const float*)d_in[9];
    const float* b3  = (const float*)d_in[10];
    const float* Wn1 = (const float*)d_in[11];
    const float* bn1 = (const float*)d_in[12];
    const float* Wn2 = (const float*)d_in[13];
    const float* bn2 = (const float*)d_in[14];
    float* out = (float*)d_out;

    const int edge_smem = (257 * HID + HID * HID + HID * W3_PAD + HID + HID + W3_PAD) * 4;
    const int node_smem = (2 * SD * HID + HID * SD + HID + SD) * 4;
    cudaFuncSetAttribute(edge_kernel, cudaFuncAttributeMaxDynamicSharedMemorySize, edge_smem);
    cudaFuncSetAttribute(node_kernel, cudaFuncAttributeMaxDynamicSharedMemorySize, node_smem);

    init_state<<<1024, 256>>>(s, v);
    prep_edges<<<(N_EDGES + 255) / 256, 256>>>(ei, d);
    compute_inv<<<(N_NODES + 255) / 256, 256>>>();

    for (int l = 0; l < DEPTH; l++) {
        zero_agg<<<1024, 256>>>();
        edge_kernel<<<(N_EDGES + 255) / 256, 256, edge_smem>>>(ei, d, r, W1, b1, W2, b2, W3, b3, l);
        node_kernel<<<(N_NODES + 255) / 256, 256, node_smem>>>(Wn1, bn1, Wn2, bn2, l);
    }
    write_out<<<1024, 256>>>(out);
}

// round 5
// speedup vs baseline: 1.9435x; 1.5801x over previous
#include <cuda_runtime.h>
#include <cstdint>

#define N_NODES 50000
#define N_EDGES 500000
#define SD 128
#define VD 3
#define HID 64
#define DEPTH 4
#define CUTOFF 5.0f

#define W3_PAD 136

// ---------------- scratch state ----------------
__device__ float g_s[N_NODES * SD];
__device__ float g_v[N_NODES * VD * 3];
__device__ float g_sagg[N_NODES * SD];
__device__ float g_vagg[N_NODES * VD * 3];
__device__ float g_cnt[N_NODES];
__device__ float g_inv[N_NODES];
__device__ float g_C[N_EDGES];
__device__ float g_ha[N_NODES * HID];   // s @ W1[0:128]  + b1
__device__ float g_hb[N_NODES * HID];   // s @ W1[128:256]

__device__ __forceinline__ float silu(float x) {
    return x / (1.0f + __expf(-x));
}

// ---------------- packed f32x2 helpers ----------------
__device__ __forceinline__ unsigned long long pack2(float x) {
    unsigned long long p;
    unsigned int u = __float_as_uint(x);
    asm("mov.b64 %0, {%1, %1};" : "=l"(p) : "r"(u));
    return p;
}
__device__ __forceinline__ void unpack2(unsigned long long p, float& lo, float& hi) {
    unsigned int a, b;
    asm("mov.b64 {%0, %1}, %2;" : "=r"(a), "=r"(b) : "l"(p));
    lo = __uint_as_float(a);
    hi = __uint_as_float(b);
}
__device__ __forceinline__ void fma2(unsigned long long& acc,
                                     unsigned long long a, unsigned long long b) {
    asm("fma.rn.f32x2 %0, %1, %2, %0;" : "+l"(acc) : "l"(a), "l"(b));
}
__device__ __forceinline__ unsigned long long mul2(unsigned long long a,
                                                   unsigned long long b) {
    unsigned long long d;
    asm("mul.rn.f32x2 %0, %1, %2;" : "=l"(d) : "l"(a), "l"(b));
    return d;
}

__device__ __forceinline__ void red_add4(float* p, float a, float b, float c, float d) {
    asm volatile("red.global.add.v4.f32 [%0], {%1,%2,%3,%4};"
                 :: "l"(p), "f"(a), "f"(b), "f"(c), "f"(d) : "memory");
}
__device__ __forceinline__ void red_add1(float* p, float a) {
    asm volatile("red.global.add.f32 [%0], %1;" :: "l"(p), "f"(a) : "memory");
}

// ---------------- prep kernels ----------------
__global__ void init_state(const float* __restrict__ s, const float* __restrict__ v) {
    int i = blockIdx.x * blockDim.x + threadIdx.x;
    int stride = gridDim.x * blockDim.x;
    for (int k = i; k < N_NODES * SD; k += stride) g_s[k] = s[k];
    for (int k = i; k < N_NODES * VD * 3; k += stride) g_v[k] = v[k];
    for (int k = i; k < N_NODES; k += stride) g_cnt[k] = 0.0f;
}

__global__ void prep_edges(const int* __restrict__ ei, const float* __restrict__ d) {
    int e = blockIdx.x * blockDim.x + threadIdx.x;
    if (e >= N_EDGES) return;
    int dst = ei[e];
    red_add1(&g_cnt[dst], 1.0f);
    float dd = d[e];
    float c = 0.5f * (cospif(dd * (1.0f / CUTOFF)) + 1.0f);
    g_C[e] = (dd < CUTOFF) ? c : 0.0f;
}

__global__ void compute_inv() {
    int n = blockIdx.x * blockDim.x + threadIdx.x;
    if (n < N_NODES) g_inv[n] = 1.0f / fmaxf(g_cnt[n], 1.0f);
}

__global__ void zero_agg() {
    int i = blockIdx.x * blockDim.x + threadIdx.x;
    int stride = gridDim.x * blockDim.x;
    for (int k = i; k < N_NODES * SD; k += stride) g_sagg[k] = 0.0f;
    for (int k = i; k < N_NODES * VD * 3; k += stride) g_vagg[k] = 0.0f;
}

// ---------------- per-node W1 precompute: ha = s@W1a + b1, hb = s@W1b ------
// W1 layout (257, 64): rows 0..127 -> dst half, 128..255 -> src half, 256 -> wd
__global__ __launch_bounds__(256) void precompute_h(
    const float* __restrict__ W1, const float* __restrict__ b1, int layer)
{
    extern __shared__ float sm[];
    float* W1s = sm;              // 256*64 floats
    float* b1s = W1s + 256 * HID; // 64

    const float* W1g = W1 + (size_t)layer * 257 * HID;
    for (int i = threadIdx.x; i < 256 * HID; i += blockDim.x) W1s[i] = W1g[i];
    for (int i = threadIdx.x; i < HID; i += blockDim.x) b1s[i] = b1[layer * HID + i];
    __syncthreads();

    int n = blockIdx.x * blockDim.x + threadIdx.x;
    if (n >= N_NODES) return;

    const float4* xs = reinterpret_cast<const float4*>(g_s + (size_t)n * SD);

    // ---- ha ----
    unsigned long long acc[32];
    {
        const unsigned long long* bp = (const unsigned long long*)b1s;
#pragma unroll
        for (int q = 0; q < 32; q++) acc[q] = bp[q];
    }
#pragma unroll 4
    for (int kk = 0; kk < SD / 4; kk++) {
        float4 xv = xs[kk];
        float xr[4] = {xv.x, xv.y, xv.z, xv.w};
#pragma unroll
        for (int t = 0; t < 4; t++) {
            unsigned long long xk2 = pack2(xr[t]);
            const ulonglong2* wrow = reinterpret_cast<const ulonglong2*>(W1s + (kk * 4 + t) * HID);
#pragma unroll
            for (int q = 0; q < 16; q++) {
                ulonglong2 w = wrow[q];
                fma2(acc[2 * q + 0], xk2, w.x);
                fma2(acc[2 * q + 1], xk2, w.y);
            }
        }
    }
    {
        float* hap = g_ha + (size_t)n * HID;
#pragma unroll
        for (int q = 0; q < 32; q++) {
            float lo, hi;
            unpack2(acc[q], lo, hi);
            hap[2 * q + 0] = lo;
            hap[2 * q + 1] = hi;
        }
    }

    // ---- hb ----
#pragma unroll
    for (int q = 0; q < 32; q++) acc[q] = 0ULL;
#pragma unroll 4
    for (int kk = 0; kk < SD / 4; kk++) {
        float4 xv = xs[kk];
        float xr[4] = {xv.x, xv.y, xv.z, xv.w};
#pragma unroll
        for (int t = 0; t < 4; t++) {
            unsigned long long xk2 = pack2(xr[t]);
            const ulonglong2* wrow = reinterpret_cast<const ulonglong2*>(W1s + (SD + kk * 4 + t) * HID);
#pragma unroll
            for (int q = 0; q < 16; q++) {
                ulonglong2 w = wrow[q];
                fma2(acc[2 * q + 0], xk2, w.x);
                fma2(acc[2 * q + 1], xk2, w.y);
            }
        }
    }
    {
        float* hbp = g_hb + (size_t)n * HID;
#pragma unroll
        for (int q = 0; q < 32; q++) {
            float lo, hi;
            unpack2(acc[q], lo, hi);
            hbp[2 * q + 0] = lo;
            hbp[2 * q + 1] = hi;
        }
    }
}

// ---------------- fused edge MLP + scatter ----------------
// h1 = silu(ha[dst] + hb[src] + d*wd); h2 = silu(h1@W2+b2); m = h2@W3+b3
__global__ __launch_bounds__(256, 2) void edge_kernel(
    const int* __restrict__ ei, const float* __restrict__ d, const float* __restrict__ r,
    const float* __restrict__ W1,
    const float* __restrict__ W2, const float* __restrict__ b2,
    const float* __restrict__ W3, const float* __restrict__ b3, int layer)
{
    extern __shared__ float sm[];
    float* W2s = sm;                 // 64*64
    float* W3s = W2s + HID * HID;    // 64*136
    float* wds = W3s + HID * W3_PAD; // 64 (W1 row 256)
    float* b2s = wds + HID;          // 64
    float* b3s = b2s + HID;          // 136

    const float* W2g = W2 + (size_t)layer * HID * HID;
    const float* W3g = W3 + (size_t)layer * HID * 134;
    const float* wdg = W1 + (size_t)layer * 257 * HID + 256 * HID;

    for (int i = threadIdx.x; i < HID * HID; i += blockDim.x) W2s[i] = W2g[i];
    for (int i = threadIdx.x; i < HID * 134; i += blockDim.x) {
        int row = i / 134, col = i - row * 134;
        W3s[row * W3_PAD + col] = W3g[i];
    }
    for (int i = threadIdx.x; i < HID; i += blockDim.x) {
        wds[i] = wdg[i];
        b2s[i] = b2[layer * HID + i];
    }
    for (int i = threadIdx.x; i < 134; i += blockDim.x) b3s[i] = b3[layer * 134 + i];
    __syncthreads();

    int e = blockIdx.x * blockDim.x + threadIdx.x;
    if (e >= N_EDGES) return;

    int dst = ei[e];
    int src = ei[N_EDGES + e];
    float C = g_C[e];
    float de = d[e];

    // ---- h1 ----
    float h1[HID];
    {
        const float4* ap = reinterpret_cast<const float4*>(g_ha + (size_t)dst * HID);
        const float4* bp = reinterpret_cast<const float4*>(g_hb + (size_t)src * HID);
        const float4* wp = reinterpret_cast<const float4*>(wds);
#pragma unroll
        for (int q = 0; q < HID / 4; q++) {
            float4 a = ap[q], b = bp[q], w = wp[q];
            h1[4 * q + 0] = silu(fmaf(de, w.x, a.x + b.x));
            h1[4 * q + 1] = silu(fmaf(de, w.y, a.y + b.y));
            h1[4 * q + 2] = silu(fmaf(de, w.z, a.z + b.z));
            h1[4 * q + 3] = silu(fmaf(de, w.w, a.w + b.w));
        }
    }

    // ---- h2 = silu(h1 @ W2 + b2), two 32-output halves to bound registers ----
    float h2[HID];
#pragma unroll 1
    for (int half = 0; half < 2; half++) {
        unsigned long long acc[16];
        const unsigned long long* bp = (const unsigned long long*)(b2s + half * 32);
#pragma unroll
        for (int q = 0; q < 16; q++) acc[q] = bp[q];
#pragma unroll 4
        for (int k = 0; k < HID; k++) {
            unsigned long long hk2 = pack2(h1[k]);
            const ulonglong2* wrow = reinterpret_cast<const ulonglong2*>(W2s + k * HID + half * 32);
#pragma unroll
            for (int q = 0; q < 8; q++) {
                ulonglong2 w = wrow[q];
                fma2(acc[2 * q + 0], hk2, w.x);
                fma2(acc[2 * q + 1], hk2, w.y);
            }
        }
#pragma unroll
        for (int q = 0; q < 16; q++) {
            float lo, hi;
            unpack2(acc[q], lo, hi);
            h2[half * 32 + 2 * q + 0] = silu(lo);
            h2[half * 32 + 2 * q + 1] = silu(hi);
        }
    }

    // ---- m = h2 @ W3 + b3 ; scatter ----
    unsigned long long C2 = pack2(C);
    float* sbase = g_sagg + (size_t)dst * SD;

    unsigned long long g01, g23, g45;
    {
        const unsigned long long* gp = (const unsigned long long*)(b3s + SD);
        g01 = gp[0]; g23 = gp[1]; g45 = gp[2];
    }

#pragma unroll 1
    for (int c = 0; c < 4; c++) {
        unsigned long long acc[16];
        const unsigned long long* bp = (const unsigned long long*)(b3s + c * 32);
#pragma unroll
        for (int q = 0; q < 16; q++) acc[q] = bp[q];

        if (c == 0) {
#pragma unroll 4
            for (int k = 0; k < HID; k++) {
                unsigned long long hk2 = pack2(h2[k]);
                const ulonglong2* wrow = reinterpret_cast<const ulonglong2*>(W3s + k * W3_PAD);
#pragma unroll
                for (int q = 0; q < 8; q++) {
                    ulonglong2 w = wrow[q];
                    fma2(acc[2 * q + 0], hk2, w.x);
                    fma2(acc[2 * q + 1], hk2, w.y);
                }
                const unsigned long long* gw = (const unsigned long long*)(W3s + k * W3_PAD + SD);
                fma2(g01, hk2, gw[0]);
                fma2(g23, hk2, gw[1]);
                fma2(g45, hk2, gw[2]);
            }
        } else {
#pragma unroll 4
            for (int k = 0; k < HID; k++) {
                unsigned long long hk2 = pack2(h2[k]);
                const ulonglong2* wrow = reinterpret_cast<const ulonglong2*>(W3s + k * W3_PAD + c * 32);
#pragma unroll
                for (int q = 0; q < 8; q++) {
                    ulonglong2 w = wrow[q];
                    fma2(acc[2 * q + 0], hk2, w.x);
                    fma2(acc[2 * q + 1], hk2, w.y);
                }
            }
        }
#pragma unroll
        for (int q = 0; q < 8; q++) {
            unsigned long long p0 = mul2(acc[2 * q + 0], C2);
            unsigned long long p1 = mul2(acc[2 * q + 1], C2);
            float a0, a1, a2, a3;
            unpack2(p0, a0, a1);
            unpack2(p1, a2, a3);
            red_add4(sbase + c * 32 + q * 4, a0, a1, a2, a3);
        }
    }

    // vector part
    float g6[6];
    unpack2(g01, g6[0], g6[1]);
    unpack2(g23, g6[2], g6[3]);
    unpack2(g45, g6[4], g6[5]);

    float rr0 = r[e * 3 + 0], rr1 = r[e * 3 + 1], rr2 = r[e * 3 + 2];
    const float* vs = g_v + (size_t)src * 9;
    float* vdp = g_vagg + (size_t)dst * 9;
#pragma unroll
    for (int a = 0; a < 3; a++) {
        float gva = g6[a] * C, gra = g6[3 + a] * C;
        red_add1(vdp + a * 3 + 0, vs[a * 3 + 0] * gva + rr0 * gra);
        red_add1(vdp + a * 3 + 1, vs[a * 3 + 1] * gva + rr1 * gra);
        red_add1(vdp + a * 3 + 2, vs[a * 3 + 2] * gva + rr2 * gra);
    }
}

// ---------------- fused node MLP + residual updates ----------------
__global__ __launch_bounds__(256) void node_kernel(
    const float* __restrict__ Wn1, const float* __restrict__ bn1,
    const float* __restrict__ Wn2, const float* __restrict__ bn2, int layer)
{
    extern __shared__ float sm[];
    float* W1s = sm;                     // 256*64
    float* W2s = W1s + 2 * SD * HID;     // 64*128
    float* b1s = W2s + HID * SD;         // 64
    float* b2s = b1s + HID;              // 128

    const float* W1g = Wn1 + (size_t)layer * 2 * SD * HID;
    const float* W2g = Wn2 + (size_t)layer * HID * SD;
    for (int i = threadIdx.x; i < 2 * SD * HID; i += blockDim.x) W1s[i] = W1g[i];
    for (int i = threadIdx.x; i < HID * SD; i += blockDim.x) W2s[i] = W2g[i];
    for (int i = threadIdx.x; i < HID; i += blockDim.x) b1s[i] = bn1[layer * HID + i];
    for (int i = threadIdx.x; i < SD; i += blockDim.x) b2s[i] = bn2[layer * SD + i];
    __syncthreads();

    int n = blockIdx.x * blockDim.x + threadIdx.x;
    if (n >= N_NODES) return;

    unsigned long long up[32];
    {
        const unsigned long long* b1p = (const unsigned long long*)b1s;
#pragma unroll
        for (int j = 0; j < 32; j++) up[j] = b1p[j];
    }

    const float4* xs = reinterpret_cast<const float4*>(g_s + (size_t)n * SD);
    const float4* xa = reinterpret_cast<const float4*>(g_sagg + (size_t)n * SD);

#pragma unroll 4
    for (int kk = 0; kk < SD / 4; kk++) {
        float4 xv = xs[kk];
        float xr[4] = {xv.x, xv.y, xv.z, xv.w};
#pragma unroll
        for (int t = 0; t < 4; t++) {
            unsigned long long xk2 = pack2(xr[t]);
            const ulonglong2* wrow = reinterpret_cast<const ulonglong2*>(W1s + (kk * 4 + t) * HID);
#pragma unroll
            for (int q = 0; q < 16; q++) {
                ulonglong2 w = wrow[q];
                fma2(up[2 * q + 0], xk2, w.x);
                fma2(up[2 * q + 1], xk2, w.y);
            }
        }
    }
#pragma unroll 4
    for (int kk = 0; kk < SD / 4; kk++) {
        float4 xv = xa[kk];
        float xr[4] = {xv.x, xv.y, xv.z, xv.w};
#pragma unroll
        for (int t = 0; t < 4; t++) {
            unsigned long long xk2 = pack2(xr[t]);
            const ulonglong2* wrow = reinterpret_cast<const ulonglong2*>(W1s + (SD + kk * 4 + t) * HID);
#pragma unroll
            for (int q = 0; q < 16; q++) {
                ulonglong2 w = wrow[q];
                fma2(up[2 * q + 0], xk2, w.x);
                fma2(up[2 * q + 1], xk2, w.y);
            }
        }
    }

    float u[HID];
#pragma unroll
    for (int j = 0; j < 32; j++) {
        float lo, hi;
        unpack2(up[j], lo, hi);
        u[2 * j + 0] = silu(lo);
        u[2 * j + 1] = silu(hi);
    }

    float* sp = g_s + (size_t)n * SD;
#pragma unroll 1
    for (int c = 0; c < 4; c++) {
        unsigned long long acc[16];
        const unsigned long long* bp = (const unsigned long long*)(b2s + c * 32);
#pragma unroll
        for (int q = 0; q < 16; q++) acc[q] = bp[q];
#pragma unroll 4
        for (int k = 0; k < HID; k++) {
            unsigned long long hk2 = pack2(u[k]);
            const ulonglong2* wrow = reinterpret_cast<const ulonglong2*>(W2s + k * SD + c * 32);
#pragma unroll
            for (int q = 0; q < 8; q++) {
                ulonglong2 w = wrow[q];
                fma2(acc[2 * q + 0], hk2, w.x);
                fma2(acc[2 * q + 1], hk2, w.y);
            }
        }
#pragma unroll
        for (int q = 0; q < 16; q++) {
            float lo, hi;
            unpack2(acc[q], lo, hi);
            sp[c * 32 + 2 * q + 0] += lo;
            sp[c * 32 + 2 * q + 1] += hi;
        }
    }

    float inv = g_inv[n];
    float* vp = g_v + (size_t)n * 9;
    const float* va = g_vagg + (size_t)n * 9;
#pragma unroll
    for (int i = 0; i < 9; i++) vp[i] += va[i] * inv;
}

__global__ void write_out(float* __restrict__ out) {
    int i = blockIdx.x * blockDim.x + threadIdx.x;
    int stride = gridDim.x * blockDim.x;
    for (int k = i; k < N_NODES * SD; k += stride) out[k] = g_s[k];
    for (int k = i; k < N_NODES * VD * 3; k += stride) out[N_NODES * SD + k] = g_v[k];
}

// ---------------- launch ----------------
extern "C" void kernel_launch(void* const* d_in, const int* in_sizes, int n_in,
                              void* d_out, int out_size) {
    const float* s   = (const float*)d_in[0];
    const float* v   = (const float*)d_in[1];
    const int*   ei  = (const int*)d_in[2];
    const float* d   = (const float*)d_in[3];
    const float* r   = (const float*)d_in[4];
    const float* W1  = (const float*)d_in[5];
    const float* b1  = (const float*)d_in[6];
    const float* W2  = (const float*)d_in[7];
    const float* b2  = (const float*)d_in[8];
    const float* W3  = (const float*)d_in[9];
    const float* b3  = (const float*)d_in[10];
    const float* Wn1 = (const float*)d_in[11];
    const float* bn1 = (const float*)d_in[12];
    const float* Wn2 = (const float*)d_in[13];
    const float* bn2 = (const float*)d_in[14];
    float* out = (float*)d_out;

    const int pre_smem  = (256 * HID + HID) * 4;
    const int edge_smem = (HID * HID + HID * W3_PAD + HID + HID + W3_PAD) * 4;
    const int node_smem = (2 * SD * HID + HID * SD + HID + SD) * 4;
    cudaFuncSetAttribute(precompute_h, cudaFuncAttributeMaxDynamicSharedMemorySize, pre_smem);
    cudaFuncSetAttribute(edge_kernel, cudaFuncAttributeMaxDynamicSharedMemorySize, edge_smem);
    cudaFuncSetAttribute(node_kernel, cudaFuncAttributeMaxDynamicSharedMemorySize, node_smem);

    init_state<<<1024, 256>>>(s, v);
    prep_edges<<<(N_EDGES + 255) / 256, 256>>>(ei, d);
    compute_inv<<<(N_NODES + 255) / 256, 256>>>();

    for (int l = 0; l < DEPTH; l++) {
        precompute_h<<<(N_NODES + 255) / 256, 256, pre_smem>>>(W1, b1, l);
        zero_agg<<<1024, 256>>>();
        edge_kernel<<<(N_EDGES + 255) / 256, 256, edge_smem>>>(ei, d, r, W1, W2, b2, W3, b3, l);
        node_kernel<<<(N_NODES + 255) / 256, 256, node_smem>>>(Wn1, bn1, Wn2, bn2, l);
    }
    write_out<<<1024, 256>>>(out);
}